// round 7
// baseline (speedup 1.0000x reference)
#include <cuda_runtime.h>
#include <cstdint>

#define BB 8
#define CC 14
#define HH 512
#define WW 512
#define PP (HH * WW)              // 262144
#define KK 13                     // classes 1..13
#define NBK (BB * KK)             // 104
#define THREADS 512
#define SEG 1024                  // pixels per block segment
#define SEGS_PER_IMG (PP / SEG)   // 256
#define GRID_BLOCKS (BB * SEGS_PER_IMG)   // 2048
#define STAGES 4
#define STAGE_BYTES (SEG * 4)     // 4096 B per plane-segment
#define TX_BYTES (2 * STAGE_BYTES)// S + T per stage

// Global scratch. Zero-initialized at module load; last block resets after
// consuming, so every invocation starts from zeros.
__device__ float        g_kl[NBK];
__device__ unsigned int g_n[NBK];
__device__ unsigned int g_flag[NBK];
__device__ unsigned int g_count;

static __device__ __forceinline__ unsigned int smem_u32(const void* p) {
    unsigned int a;
    asm("{ .reg .u64 t; cvta.to.shared.u64 t, %1; cvt.u32.u64 %0, t; }"
        : "=r"(a) : "l"(p));
    return a;
}

static __device__ __forceinline__ void mbar_init(unsigned int mbar, unsigned int cnt) {
    asm volatile("mbarrier.init.shared.b64 [%0], %1;" :: "r"(mbar), "r"(cnt) : "memory");
}

static __device__ __forceinline__ void mbar_expect_tx(unsigned int mbar, unsigned int bytes) {
    asm volatile("mbarrier.arrive.expect_tx.shared.b64 _, [%0], %1;"
                 :: "r"(mbar), "r"(bytes) : "memory");
}

static __device__ __forceinline__ void mbar_wait(unsigned int mbar, unsigned int phase) {
    asm volatile(
        "{\n\t"
        ".reg .pred P;\n\t"
        "WL%=:\n\t"
        "mbarrier.try_wait.parity.acquire.cta.shared::cta.b64 P, [%0], %1, 0x989680;\n\t"
        "@!P bra WL%=;\n\t"
        "}"
        :: "r"(mbar), "r"(phase) : "memory");
}

static __device__ __forceinline__ void bulk_g2s(unsigned int dst, const void* src,
                                                unsigned int bytes, unsigned int mbar) {
    asm volatile(
        "cp.async.bulk.shared::cluster.global.mbarrier::complete_tx::bytes "
        "[%0], [%1], %2, [%3];"
        :: "r"(dst), "l"(src), "r"(bytes), "r"(mbar) : "memory");
}

__global__ void __launch_bounds__(THREADS, 3) bkd_tma_kernel(
    const float* __restrict__ S,
    const float* __restrict__ T,
    const int*   __restrict__ gt,
    float*       __restrict__ out)
{
    __shared__ alignas(1024) float sS[STAGES][SEG];
    __shared__ alignas(1024) float sT[STAGES][SEG];
    __shared__ alignas(8) unsigned long long mbar_store[STAGES];
    __shared__ float        s_kl[KK];
    __shared__ unsigned int s_n[KK];
    __shared__ unsigned int s_flag[KK];
    __shared__ unsigned int s_isLast;

    const int tid = threadIdx.x;
    if (tid < KK) {
        s_kl[tid]   = 0.0f;
        s_n[tid]    = 0u;
        s_flag[tid] = 0u;
    }
    const unsigned int mb0 = smem_u32(&mbar_store[0]);
    if (tid == 0) {
#pragma unroll
        for (int i = 0; i < STAGES; i++) mbar_init(mb0 + 8u * i, 1u);
    }
    __syncthreads();   // barriers + s_* visible before any TMA / use

    const int b    = blockIdx.x >> 8;          // / SEGS_PER_IMG
    const int seg  = blockIdx.x & (SEGS_PER_IMG - 1);
    const int base = seg * SEG;                // pixel offset within image

    const float* Sb = S + ((size_t)b * CC) * PP + base;
    const float* Tb = T + ((size_t)b * CC) * PP + base;

    // ---- prime the pipeline: stages 0..3 hold channels 0..3 ----
    if (tid == 0) {
#pragma unroll
        for (int i = 0; i < STAGES; i++) {
            unsigned int mb = mb0 + 8u * i;
            mbar_expect_tx(mb, TX_BYTES);
            bulk_g2s(smem_u32(&sS[i][0]), Sb + (size_t)i * PP, STAGE_BYTES, mb);
            bulk_g2s(smem_u32(&sT[i][0]), Tb + (size_t)i * PP, STAGE_BYTES, mb);
        }
    }

    // ---- boundary detection (plain LDG, overlaps with TMA flight) ----
    const int hw = base + (tid << 1);          // 2 pixels per thread
    const int h  = hw >> 9;
    const int w  = hw & 511;
    const int* gtb = gt + (size_t)b * PP;
    int2 gc = *(const int2*)(gtb + hw);
    int2 gu = (h > 0)      ? *(const int2*)(gtb + hw - WW) : make_int2(-1, -1);
    int2 gd = (h < HH - 1) ? *(const int2*)(gtb + hw + WW) : make_int2(-1, -1);
    int gl = (w > 0)       ? gtb[hw - 1] : -1;
    int gr = (w + 2 < WW)  ? gtb[hw + 2] : -1;

    const bool bnd0 = (gc.x >= 1) &&
                      (gu.x != gc.x || gd.x != gc.x || gl   != gc.x || gc.y != gc.x);
    const bool bnd1 = (gc.y >= 1) &&
                      (gu.y != gc.y || gd.y != gc.y || gc.x != gc.y || gr   != gc.y);

    // ---- mainloop: consume stage, then refill it 4 channels ahead ----
    // kl = A/Z_T + log(Z_S/Z_T)
    float ZS0 = 0.f, ZS1 = 0.f;
    float ZT0 = 0.f, ZT1 = 0.f;
    float A0  = 0.f, A1  = 0.f;

#pragma unroll
    for (int c = 0; c < CC; c++) {
        const int st = c & (STAGES - 1);
        const int ph = (c >> 2) & 1;
        mbar_wait(mb0 + 8u * st, (unsigned)ph);

        float2 xs = *(const float2*)&sS[st][tid << 1];
        float2 xt = *(const float2*)&sT[st][tid << 1];

        float es0 = __expf(xs.x), et0 = __expf(xt.x);
        float es1 = __expf(xs.y), et1 = __expf(xt.y);
        ZS0 += es0; ZT0 += et0; A0 = fmaf(et0, xt.x - xs.x, A0);
        ZS1 += es1; ZT1 += et1; A1 = fmaf(et1, xt.y - xs.y, A1);

        __syncthreads();                       // all consumed stage st for channel c
        if (c + STAGES < CC && tid == 0) {
            asm volatile("fence.proxy.async.shared::cta;" ::: "memory");
            unsigned int mb = mb0 + 8u * st;
            mbar_expect_tx(mb, TX_BYTES);
            bulk_g2s(smem_u32(&sS[st][0]), Sb + (size_t)(c + STAGES) * PP, STAGE_BYTES, mb);
            bulk_g2s(smem_u32(&sT[st][0]), Tb + (size_t)(c + STAGES) * PP, STAGE_BYTES, mb);
        }
    }

    // ---- per-block shared accumulation into 13 class bins ----
    if (bnd0) {
        float r  = __fdividef(1.0f, ZT0);
        float kl = A0 * r + __logf(ZS0 * r);
        int k = gc.x - 1;
        atomicAdd(&s_kl[k], kl);
        atomicAdd(&s_n[k], 1u);
        if (hw > 0) s_flag[k] = 1u;            // idempotent racing write
    }
    if (bnd1) {
        float r  = __fdividef(1.0f, ZT1);
        float kl = A1 * r + __logf(ZS1 * r);
        int k = gc.y - 1;
        atomicAdd(&s_kl[k], kl);
        atomicAdd(&s_n[k], 1u);
        s_flag[k] = 1u;                        // hw+1 > 0 always
    }
    __syncthreads();

    if (tid < KK) {
        int k   = tid;
        int idx = b * KK + k;
        if (s_n[k] > 0u) {
            atomicAdd(&g_kl[idx], s_kl[k]);
            atomicAdd(&g_n[idx],  s_n[k]);
        }
        if (s_flag[k]) atomicOr(&g_flag[idx], 1u);
    }

    // ---- last-block-done finalize (fused reduction + scratch reset) ----
    __threadfence();
    if (tid == 0) {
        unsigned int v = atomicAdd(&g_count, 1u);
        s_isLast = (v == (unsigned int)(GRID_BLOCKS - 1)) ? 1u : 0u;
    }
    __syncthreads();

    if (s_isLast) {
        float* sred = &sS[0][0];               // reuse stage buffer as scratch
        float t = 0.0f;
        if (tid < NBK && g_flag[tid]) {
            unsigned int n = g_n[tid];
            if (n < 1u) n = 1u;
            t = g_kl[tid] / (14.0f * (float)n);
        }
        sred[tid] = t;
        __syncthreads();
#pragma unroll
        for (int s = 256; s > 0; s >>= 1) {
            if (tid < s) sred[tid] += sred[tid + s];
            __syncthreads();
        }
        if (tid == 0) {
            out[0] = sred[0];                  // LOSS_WEIGHT * TAU^2 == 1
            g_count = 0u;                      // reset for next replay
        }
        if (tid < NBK) {
            g_kl[tid]   = 0.0f;
            g_n[tid]    = 0u;
            g_flag[tid] = 0u;
        }
    }
}

extern "C" void kernel_launch(void* const* d_in, const int* in_sizes, int n_in,
                              void* d_out, int out_size) {
    const float* S  = (const float*)d_in[0];
    const float* T  = (const float*)d_in[1];
    const int*   gt = (const int*)d_in[2];
    float* out = (float*)d_out;

    bkd_tma_kernel<<<GRID_BLOCKS, THREADS>>>(S, T, gt, out);
}

// round 8
// speedup vs baseline: 1.2596x; 1.2596x over previous
#include <cuda_runtime.h>

#define BB 8
#define CC 14
#define HH 512
#define WW 512
#define PP (HH * WW)          // 262144 = 2^18
#define KK 13                 // classes 1..13
#define NBK (BB * KK)         // 104
#define THREADS 256
#define GRID_BLOCKS ((BB * PP / 2) / THREADS)   // 4096
#define DEPTH 6               // software-pipeline depth (channels prefetched)

// Global scratch. Zero-initialized at module load; the last block resets
// them after consuming, so every invocation starts from zeros.
__device__ float        g_kl[NBK];
__device__ unsigned int g_n[NBK];
__device__ unsigned int g_flag[NBK];
__device__ unsigned int g_count;

__global__ void __launch_bounds__(THREADS, 5) bkd_fused_kernel(
    const float* __restrict__ S,
    const float* __restrict__ T,
    const int*   __restrict__ gt,
    float*       __restrict__ out)
{
    __shared__ float        s_kl[KK];
    __shared__ unsigned int s_n[KK];
    __shared__ unsigned int s_flag[KK];
    __shared__ unsigned int s_isLast;
    if (threadIdx.x < KK) {
        s_kl[threadIdx.x]   = 0.0f;
        s_n[threadIdx.x]    = 0u;
        s_flag[threadIdx.x] = 0u;
    }
    __syncthreads();

    const int tid = blockIdx.x * blockDim.x + threadIdx.x;
    const int p0  = tid << 1;                // 2 pixels per thread
    const int b   = p0 >> 18;                // / PP
    const int hw  = p0 & (PP - 1);
    const int h   = hw >> 9;                 // / 512
    const int w   = hw & 511;

    const float* Sp = S + (size_t)b * CC * PP + hw;
    const float* Tp = T + (size_t)b * CC * PP + hw;

    // ---- prime the pipeline: issue first DEPTH channels of loads ----
    float2 bs[DEPTH], bt[DEPTH];
#pragma unroll
    for (int i = 0; i < DEPTH; i++) {
        bs[i] = __ldcs((const float2*)(Sp + (size_t)i * PP));
        bt[i] = __ldcs((const float2*)(Tp + (size_t)i * PP));
    }

    // ---- boundary detection (overlaps with in-flight S/T loads) ----
    const int* gtb = gt + (size_t)b * PP;
    int2 gc = *(const int2*)(gtb + hw);
    int2 gu = (h > 0)      ? *(const int2*)(gtb + hw - WW) : make_int2(-1, -1);
    int2 gd = (h < HH - 1) ? *(const int2*)(gtb + hw + WW) : make_int2(-1, -1);
    int gl = (w > 0)       ? gtb[hw - 1] : -1;
    int gr = (w + 2 < WW)  ? gtb[hw + 2] : -1;

    const bool bnd0 = (gc.x >= 1) &&
                      (gu.x != gc.x || gd.x != gc.x || gl   != gc.x || gc.y != gc.x);
    const bool bnd1 = (gc.y >= 1) &&
                      (gu.y != gc.y || gd.y != gc.y || gc.x != gc.y || gr   != gc.y);

    // ---- pipelined single-pass softmax/KL accumulation ----
    // kl = A/Z_T + log(Z_S/Z_T)
    float ZS0 = 0.f, ZS1 = 0.f;
    float ZT0 = 0.f, ZT1 = 0.f;
    float A0  = 0.f, A1  = 0.f;

#pragma unroll
    for (int c = 0; c < CC; c++) {
        const int slot = c % DEPTH;           // constant after full unroll
        float2 xs = bs[slot];
        float2 xt = bt[slot];
        if (c + DEPTH < CC) {                 // issue next loads BEFORE compute
            bs[slot] = __ldcs((const float2*)(Sp + (size_t)(c + DEPTH) * PP));
            bt[slot] = __ldcs((const float2*)(Tp + (size_t)(c + DEPTH) * PP));
        }
        float es0 = __expf(xs.x), et0 = __expf(xt.x);
        float es1 = __expf(xs.y), et1 = __expf(xt.y);
        ZS0 += es0; ZT0 += et0; A0 = fmaf(et0, xt.x - xs.x, A0);
        ZS1 += es1; ZT1 += et1; A1 = fmaf(et1, xt.y - xs.y, A1);
    }

    // ---- per-block shared accumulation into 13 class bins ----
    if (bnd0) {
        float r  = __fdividef(1.0f, ZT0);
        float kl = A0 * r + __logf(ZS0 * r);
        int k = gc.x - 1;
        atomicAdd(&s_kl[k], kl);
        atomicAdd(&s_n[k], 1u);
        if (hw > 0) s_flag[k] = 1u;           // idempotent racing write
    }
    if (bnd1) {
        float r  = __fdividef(1.0f, ZT1);
        float kl = A1 * r + __logf(ZS1 * r);
        int k = gc.y - 1;
        atomicAdd(&s_kl[k], kl);
        atomicAdd(&s_n[k], 1u);
        s_flag[k] = 1u;                        // hw+1 > 0 always
    }
    __syncthreads();

    if (threadIdx.x < KK) {
        int k   = threadIdx.x;
        int idx = b * KK + k;
        if (s_n[k] > 0u) {
            atomicAdd(&g_kl[idx], s_kl[k]);
            atomicAdd(&g_n[idx],  s_n[k]);
        }
        if (s_flag[k]) atomicOr(&g_flag[idx], 1u);
    }

    // ---- last-block-done finalize (fused reduction + scratch reset) ----
    __threadfence();
    if (threadIdx.x == 0) {
        unsigned int v = atomicAdd(&g_count, 1u);
        s_isLast = (v == (unsigned int)(GRID_BLOCKS - 1)) ? 1u : 0u;
    }
    __syncthreads();

    if (s_isLast) {
        __shared__ float sred[256];
        int i = threadIdx.x;
        float t = 0.0f;
        if (i < NBK && g_flag[i]) {
            unsigned int n = g_n[i];
            if (n < 1u) n = 1u;
            t = g_kl[i] / (14.0f * (float)n);
        }
        sred[i] = t;
        __syncthreads();
#pragma unroll
        for (int s = 128; s > 0; s >>= 1) {
            if (i < s) sred[i] += sred[i + s];
            __syncthreads();
        }
        if (i == 0) {
            out[0] = sred[0];        // LOSS_WEIGHT * TAU^2 == 1
            g_count = 0u;            // reset for next replay
        }
        if (i < NBK) {
            g_kl[i]   = 0.0f;
            g_n[i]    = 0u;
            g_flag[i] = 0u;
        }
    }
}

extern "C" void kernel_launch(void* const* d_in, const int* in_sizes, int n_in,
                              void* d_out, int out_size) {
    const float* S  = (const float*)d_in[0];
    const float* T  = (const float*)d_in[1];
    const int*   gt = (const int*)d_in[2];
    float* out = (float*)d_out;

    bkd_fused_kernel<<<GRID_BLOCKS, THREADS>>>(S, T, gt, out);
}

// round 9
// speedup vs baseline: 1.3650x; 1.0836x over previous
#include <cuda_runtime.h>

#define BB 8
#define CC 14
#define HH 512
#define WW 512
#define PP (HH * WW)          // 262144 = 2^18
#define KK 13                 // classes 1..13
#define NBK (BB * KK)         // 104
#define THREADS 256
#define GRID_BLOCKS ((BB * PP / 2) / THREADS)   // 4096
#define DEPTH 3               // software-pipeline depth (channels prefetched)

// Global scratch. Zero-initialized at module load; the last block resets
// them after consuming, so every invocation starts from zeros.
__device__ float        g_kl[NBK];
__device__ unsigned int g_n[NBK];
__device__ unsigned int g_flag[NBK];
__device__ unsigned int g_count;

__global__ void __launch_bounds__(THREADS, 7) bkd_fused_kernel(
    const float* __restrict__ S,
    const float* __restrict__ T,
    const int*   __restrict__ gt,
    float*       __restrict__ out)
{
    __shared__ float        s_kl[KK];
    __shared__ unsigned int s_n[KK];
    __shared__ unsigned int s_flag[KK];
    __shared__ unsigned int s_isLast;
    if (threadIdx.x < KK) {
        s_kl[threadIdx.x]   = 0.0f;
        s_n[threadIdx.x]    = 0u;
        s_flag[threadIdx.x] = 0u;
    }
    __syncthreads();

    const int tid = blockIdx.x * blockDim.x + threadIdx.x;
    const int p0  = tid << 1;                // 2 pixels per thread
    const int b   = p0 >> 18;                // / PP
    const int hw  = p0 & (PP - 1);
    const int h   = hw >> 9;                 // / 512
    const int w   = hw & 511;

    const float* Sp = S + (size_t)b * CC * PP + hw;
    const float* Tp = T + (size_t)b * CC * PP + hw;

    // ---- prime the pipeline: issue first DEPTH channels of loads ----
    float2 bs[DEPTH], bt[DEPTH];
#pragma unroll
    for (int i = 0; i < DEPTH; i++) {
        bs[i] = __ldcs((const float2*)(Sp + (size_t)i * PP));
        bt[i] = __ldcs((const float2*)(Tp + (size_t)i * PP));
    }

    // ---- boundary detection (overlaps with in-flight S/T loads) ----
    const int* gtb = gt + (size_t)b * PP;
    int2 gc = *(const int2*)(gtb + hw);
    int2 gu = (h > 0)      ? *(const int2*)(gtb + hw - WW) : make_int2(-1, -1);
    int2 gd = (h < HH - 1) ? *(const int2*)(gtb + hw + WW) : make_int2(-1, -1);
    int gl = (w > 0)       ? gtb[hw - 1] : -1;
    int gr = (w + 2 < WW)  ? gtb[hw + 2] : -1;

    const bool bnd0 = (gc.x >= 1) &&
                      (gu.x != gc.x || gd.x != gc.x || gl   != gc.x || gc.y != gc.x);
    const bool bnd1 = (gc.y >= 1) &&
                      (gu.y != gc.y || gd.y != gc.y || gc.x != gc.y || gr   != gc.y);

    // ---- pipelined single-pass softmax/KL accumulation ----
    // kl = A/Z_T + log(Z_S/Z_T)
    float ZS0 = 0.f, ZS1 = 0.f;
    float ZT0 = 0.f, ZT1 = 0.f;
    float A0  = 0.f, A1  = 0.f;

#pragma unroll
    for (int c = 0; c < CC; c++) {
        const int slot = c % DEPTH;           // constant after full unroll
        float2 xs = bs[slot];
        float2 xt = bt[slot];
        if (c + DEPTH < CC) {                 // issue next loads BEFORE compute
            bs[slot] = __ldcs((const float2*)(Sp + (size_t)(c + DEPTH) * PP));
            bt[slot] = __ldcs((const float2*)(Tp + (size_t)(c + DEPTH) * PP));
        }
        float es0 = __expf(xs.x), et0 = __expf(xt.x);
        float es1 = __expf(xs.y), et1 = __expf(xt.y);
        ZS0 += es0; ZT0 += et0; A0 = fmaf(et0, xt.x - xs.x, A0);
        ZS1 += es1; ZT1 += et1; A1 = fmaf(et1, xt.y - xs.y, A1);
    }

    // ---- per-block shared accumulation into 13 class bins ----
    if (bnd0) {
        float r  = __fdividef(1.0f, ZT0);
        float kl = A0 * r + __logf(ZS0 * r);
        int k = gc.x - 1;
        atomicAdd(&s_kl[k], kl);
        atomicAdd(&s_n[k], 1u);
        if (hw > 0) s_flag[k] = 1u;           // idempotent racing write
    }
    if (bnd1) {
        float r  = __fdividef(1.0f, ZT1);
        float kl = A1 * r + __logf(ZS1 * r);
        int k = gc.y - 1;
        atomicAdd(&s_kl[k], kl);
        atomicAdd(&s_n[k], 1u);
        s_flag[k] = 1u;                        // hw+1 > 0 always
    }
    __syncthreads();

    if (threadIdx.x < KK) {
        int k   = threadIdx.x;
        int idx = b * KK + k;
        if (s_n[k] > 0u) {
            atomicAdd(&g_kl[idx], s_kl[k]);
            atomicAdd(&g_n[idx],  s_n[k]);
        }
        if (s_flag[k]) atomicOr(&g_flag[idx], 1u);
    }

    // ---- last-block-done finalize (fused reduction + scratch reset) ----
    __threadfence();
    if (threadIdx.x == 0) {
        unsigned int v = atomicAdd(&g_count, 1u);
        s_isLast = (v == (unsigned int)(GRID_BLOCKS - 1)) ? 1u : 0u;
    }
    __syncthreads();

    if (s_isLast) {
        __shared__ float sred[256];
        int i = threadIdx.x;
        float t = 0.0f;
        if (i < NBK && g_flag[i]) {
            unsigned int n = g_n[i];
            if (n < 1u) n = 1u;
            t = g_kl[i] / (14.0f * (float)n);
        }
        sred[i] = t;
        __syncthreads();
#pragma unroll
        for (int s = 128; s > 0; s >>= 1) {
            if (i < s) sred[i] += sred[i + s];
            __syncthreads();
        }
        if (i == 0) {
            out[0] = sred[0];        // LOSS_WEIGHT * TAU^2 == 1
            g_count = 0u;            // reset for next replay
        }
        if (i < NBK) {
            g_kl[i]   = 0.0f;
            g_n[i]    = 0u;
            g_flag[i] = 0u;
        }
    }
}

extern "C" void kernel_launch(void* const* d_in, const int* in_sizes, int n_in,
                              void* d_out, int out_size) {
    const float* S  = (const float*)d_in[0];
    const float* T  = (const float*)d_in[1];
    const int*   gt = (const int*)d_in[2];
    float* out = (float*)d_out;

    bkd_fused_kernel<<<GRID_BLOCKS, THREADS>>>(S, T, gt, out);
}